// round 15
// baseline (speedup 1.0000x reference)
#include <cuda_runtime.h>
#include <cuda.h>
#include <cuda_bf16.h>
#include <cstddef>
#include <cstdint>

#define NN 20000
#define NE 200000
#define NG 128

// ---------------- scratch (device globals) ----------------------------------
__device__ __align__(256) __nv_bfloat16 g_bnode[(size_t)NN * 256];
__device__ __align__(256) __nv_bfloat16 g_bedge[(size_t)NE * 256];
__device__ __align__(256) __nv_bfloat16 g_bglob[(size_t)NG * 256];
__device__ __align__(256) __nv_bfloat16 g_bn1[(size_t)NN * 256];
__device__ __align__(256) __nv_bfloat16 g_be1[(size_t)NE * 256];
__device__ __align__(256) __nv_bfloat16 g_bg1[(size_t)NG * 256];
__device__ __align__(256) __nv_bfloat16 g_bq2[(size_t)NN * 256];
__device__ __align__(256) __nv_bfloat16 g_bgin[(size_t)NG * 768];
__device__ __align__(256) __nv_bfloat16 g_bnmid[(size_t)NN * 256];
__device__ __align__(256) __nv_bfloat16 g_bemid[(size_t)NE * 256];
__device__ __align__(256) __nv_bfloat16 g_bgmid[(size_t)NG * 256];
__device__ __align__(256) __nv_bfloat16 g_wb[1048576];
__device__ __align__(256) float g_p1[(size_t)NN * 256];
__device__ __align__(256) float g_p2[(size_t)NN * 256];
__device__ __align__(256) float g_p4[(size_t)NG * 256];
__device__ __align__(256) float g_q1[(size_t)NN * 256];
__device__ __align__(256) float g_q3[(size_t)NG * 256];
__device__ __align__(256) float g_e2n[(size_t)NN * 256];
__device__ int g_eflag[1568];          // per-mtile arrival flags (2 = emid ready)
#define OFF_E2G 0
#define OFF_N2G 32768
#define OFF_NCNT 65536
#define OFF_GCE 85536
#define OFF_GCN 85664
#define SMALL_N 85792
__device__ float g_small[SMALL_N];

// ---------------- device helpers ---------------------------------------------
__device__ __forceinline__ float ssp(float x) {
    return fmaxf(x, 0.0f) + log1pf(__expf(-fabsf(x))) - 0.69314718055994531f;
}
__device__ __forceinline__ void mma_bf16(float* c,
    uint32_t a0, uint32_t a1, uint32_t a2, uint32_t a3,
    uint32_t b0, uint32_t b1)
{
    asm volatile(
        "mma.sync.aligned.m16n8k16.row.col.f32.bf16.bf16.f32 "
        "{%0,%1,%2,%3},{%4,%5,%6,%7},{%8,%9},{%0,%1,%2,%3};\n"
        : "+f"(c[0]), "+f"(c[1]), "+f"(c[2]), "+f"(c[3])
        : "r"(a0), "r"(a1), "r"(a2), "r"(a3), "r"(b0), "r"(b1));
}
__device__ __forceinline__ void ldsm4(uint32_t& r0, uint32_t& r1,
                                      uint32_t& r2, uint32_t& r3, uint32_t a) {
    asm volatile("ldmatrix.sync.aligned.m8n8.x4.shared.b16 {%0,%1,%2,%3},[%4];\n"
                 : "=r"(r0), "=r"(r1), "=r"(r2), "=r"(r3) : "r"(a));
}
__device__ __forceinline__ void red4(float* p, float a, float b, float c, float d) {
    asm volatile("red.global.add.v4.f32 [%0], {%1,%2,%3,%4};"
                 :: "l"(p), "f"(a), "f"(b), "f"(c), "f"(d) : "memory");
}
__device__ __forceinline__ void mbar_init(uint32_t mbar, uint32_t cnt) {
    asm volatile("mbarrier.init.shared.b64 [%0], %1;" :: "r"(mbar), "r"(cnt) : "memory");
}
__device__ __forceinline__ void mbar_expect(uint32_t mbar, uint32_t bytes) {
    asm volatile("mbarrier.arrive.expect_tx.shared.b64 _, [%0], %1;"
                 :: "r"(mbar), "r"(bytes) : "memory");
}
__device__ __forceinline__ void mbar_wait(uint32_t mbar, uint32_t parity) {
    asm volatile(
        "{\n\t.reg .pred P;\n\t"
        "W_%=:\n\t"
        "mbarrier.try_wait.parity.acquire.cta.shared::cta.b64 P, [%0], %1, 10000000;\n\t"
        "@P bra.uni D_%=;\n\t"
        "bra.uni W_%=;\n\t"
        "D_%=:\n\t}"
        :: "r"(mbar), "r"(parity) : "memory");
}
__device__ __forceinline__ void tma2d(uint32_t saddr, const CUtensorMap* tm,
                                      int cx, int cy, uint32_t mbar) {
    asm volatile(
        "cp.async.bulk.tensor.2d.shared::cta.global.tile.mbarrier::complete_tx::bytes "
        "[%0], [%1, {%2, %3}], [%4];"
        :: "r"(saddr), "l"(tm), "r"(cx), "r"(cy), "r"(mbar) : "memory");
}
__device__ __forceinline__ uint32_t pack2(float a, float b) {
    __nv_bfloat162 h = __floats2bfloat162_rn(a, b);
    return *(uint32_t*)&h;
}

// ---------------- zero fill ----------------------------------------------------
__global__ void zero_kernel(float* __restrict__ p, int n) {
    int i = blockIdx.x * blockDim.x + threadIdx.x;
    if (i < n) p[i] = 0.0f;
}

// ---------------- fp32 -> bf16 conversion (8 floats / thread) -------------------
__global__ __launch_bounds__(256) void convert_f2b(
    const float* __restrict__ src, __nv_bfloat16* __restrict__ dst, int n8)
{
    int i = blockIdx.x * 256 + threadIdx.x;
    if (i >= n8) return;
    float4 a = ((const float4*)src)[i * 2];
    float4 b = ((const float4*)src)[i * 2 + 1];
    uint4 o;
    o.x = pack2(a.x, a.y);
    o.y = pack2(a.z, a.w);
    o.z = pack2(b.x, b.y);
    o.w = pack2(b.z, b.w);
    ((uint4*)dst)[i] = o;
}

// ---------------- e2n mean -> bf16 ------------------------------------------------
__global__ __launch_bounds__(256) void conv_e2n()
{
    int i = blockIdx.x * 256 + threadIdx.x;
    if (i >= NN * 64) return;
    int v = i >> 6;
    float inv = 1.0f / fmaxf(g_small[OFF_NCNT + v], 1.0f);
    float4 sv = ((const float4*)g_e2n)[i];
    uint2 o;
    o.x = pack2(sv.x * inv, sv.y * inv);
    o.y = pack2(sv.z * inv, sv.w * inv);
    ((uint2*)g_bq2)[i] = o;
}

// ---------------- convert all weights to bf16 ------------------------------------
struct WSrc { const float* p[9]; };
#define WO0 0
#define WO1 65536
#define WO2 131072
#define WO3 196608
#define WO4 458752
#define WO5 655360
#define WO6 851968
#define WO7 917504
#define WO8 983040
__global__ __launch_bounds__(256) void round_weights(WSrc ws) {
    int f = (blockIdx.x * 256 + threadIdx.x) * 4;
    if (f >= 1048576) return;
    const float* sp; int base;
    if      (f < WO1) { sp = ws.p[0]; base = WO0; }
    else if (f < WO2) { sp = ws.p[1]; base = WO1; }
    else if (f < WO3) { sp = ws.p[2]; base = WO2; }
    else if (f < WO4) { sp = ws.p[3]; base = WO3; }
    else if (f < WO5) { sp = ws.p[4]; base = WO4; }
    else if (f < WO6) { sp = ws.p[5]; base = WO5; }
    else if (f < WO7) { sp = ws.p[6]; base = WO6; }
    else if (f < WO8) { sp = ws.p[7]; base = WO7; }
    else              { sp = ws.p[8]; base = WO8; }
    float4 v = *(const float4*)(sp + (f - base));
    uint2 o;
    o.x = pack2(v.x, v.y);
    o.y = pack2(v.z, v.w);
    *(uint2*)(g_wb + f) = o;
}

// ---------------- TMA-fed bf16 GEMM ----------------------------------------------
// C[M,256] = [ssp](A[M,K] @ W^T) [+R]. Block 128x128, 8 warps, warp tile 32x64,
// TBK=64 bf16 (128B rows, SW128), 3-stage TMA pipe.
// DUAL: grid.x=4 selects (tmW,Cout)/(tmW2,Cout2).
// SC=2: node->graph scatter. SC=3: fused edge combine.
// SC=4: fused node combine: o=ssp(acc + R[row] + Q3[batch[row]]), n2g scatter.
// SC=5: fused edge P3+out_e: gridDim.z=2; z=0 = P3+combine (tmA/tmW), sets flag;
//       z=1 spins on flag, then out_e GEMM (tmA2/tmW2) with ssp+residual.
#define STG_BYTES 32768u
#define SMEMSZ (3 * 32768 + 1024)

template <int ACT, int ADD, int OUTBF, int SC, int DUAL>
__global__ __launch_bounds__(256, 2) void gemm_b(
    const __grid_constant__ CUtensorMap tmA,
    const __grid_constant__ CUtensorMap tmA2,
    const __grid_constant__ CUtensorMap tmW,
    const __grid_constant__ CUtensorMap tmW2,
    const float* __restrict__ R, void* __restrict__ Cout, void* __restrict__ Cout2,
    int M, int K,
    const int* __restrict__ src, const int* __restrict__ dst,
    const int* __restrict__ batch)
{
    extern __shared__ float dsm[];
    __shared__ __align__(8) uint64_t mbar_s[3];
    uint32_t smb = (uint32_t)__cvta_generic_to_shared(dsm);
    smb = (smb + 1023u) & ~1023u;
    const uint32_t mb = (uint32_t)__cvta_generic_to_shared(mbar_s);

    const int tid = threadIdx.x;
    const int m0 = blockIdx.y * 128;
    const int zz = (SC == 5) ? (int)blockIdx.z : 0;
    const int halfW = DUAL ? (int)(blockIdx.x >> 1) : 0;
    const int n0 = DUAL ? (int)(blockIdx.x & 1) * 128 : (int)blockIdx.x * 128;
    void* Co = (DUAL && halfW) ? Cout2 : Cout;
    const CUtensorMap* wmap = ((DUAL && halfW) || (SC == 5 && zz)) ? &tmW2 : &tmW;
    const CUtensorMap* amap = (SC == 5 && zz) ? &tmA2 : &tmA;

    if (tid == 0) {
        mbar_init(mb, 1); mbar_init(mb + 8, 1); mbar_init(mb + 16, 1);
    }
    __syncthreads();

    // z=1 consumer: wait until both producer n-blocks of this m-tile finished
    if (SC == 5 && zz == 1) {
        if (tid == 0) {
            while (atomicAdd(&g_eflag[blockIdx.y], 0) < 2) __nanosleep(256);
            __threadfence();
        }
        __syncthreads();
    }

    const int KT = K / 64;
    auto issue = [&](int kt, int s) {
        uint32_t base = smb + (uint32_t)s * STG_BYTES;
        mbar_expect(mb + s * 8, STG_BYTES);
        tma2d(base, amap, kt * 64, m0, mb + s * 8);
        tma2d(base + 16384u, wmap, kt * 64, n0, mb + s * 8);
    };
    if (tid == 0) {
        int pre = KT < 3 ? KT : 3;
        for (int i = 0; i < pre; i++) issue(i, i);
    }

    const int lane = tid & 31, warp = tid >> 5;
    const int wm = (warp & 3) * 32;
    const int wn = (warp >> 2) * 64;
    const int gid = lane >> 2, tig = lane & 3;
    const int hA = (lane >> 4) & 1;
    const int hB = (lane >> 3) & 1;
    const int arow = wm + (lane & 15);
    const int brow = wn + ((lane >> 4) & 1) * 8 + (lane & 7);
    const uint32_t aAddr = smb + (uint32_t)(arow * 128);
    const uint32_t bAddr = smb + 16384u + (uint32_t)(brow * 128);
    uint32_t cA[4], cB[4];
#pragma unroll
    for (int ks = 0; ks < 4; ks++) {
        cA[ks] = (uint32_t)(((ks * 2 + hA) ^ (arow & 7)) << 4);
        cB[ks] = (uint32_t)(((ks * 2 + hB) ^ (brow & 7)) << 4);
    }

    float acc[2][8][4];
#pragma unroll
    for (int mt = 0; mt < 2; mt++)
#pragma unroll
        for (int nt = 0; nt < 8; nt++)
#pragma unroll
            for (int i = 0; i < 4; i++) acc[mt][nt][i] = 0.0f;

    for (int kt = 0; kt < KT; kt++) {
        const int s = kt % 3;
        mbar_wait(mb + s * 8, (uint32_t)((kt / 3) & 1));
        const uint32_t so = (uint32_t)s * STG_BYTES;

#pragma unroll
        for (int ks = 0; ks < 4; ks++) {
            uint32_t a[2][4];
#pragma unroll
            for (int mt = 0; mt < 2; mt++)
                ldsm4(a[mt][0], a[mt][1], a[mt][2], a[mt][3],
                      aAddr + so + (uint32_t)(mt * 2048) + cA[ks]);
            uint32_t b0[8], b1[8];
#pragma unroll
            for (int g = 0; g < 4; g++)
                ldsm4(b0[2 * g], b1[2 * g], b0[2 * g + 1], b1[2 * g + 1],
                      bAddr + so + (uint32_t)(g * 2048) + cB[ks]);
#pragma unroll
            for (int mt = 0; mt < 2; mt++)
#pragma unroll
                for (int nt = 0; nt < 8; nt++)
                    mma_bf16(acc[mt][nt], a[mt][0], a[mt][1], a[mt][2],
                             a[mt][3], b0[nt], b1[nt]);
        }
        __syncthreads();
        if (tid == 0 && kt + 3 < KT) issue(kt + 3, s);
    }

    // ================= SC=3 / SC=5(z0): fused edge combine =================
    if (SC == 3 || (SC == 5 && zz == 0)) {
        float* sacc = dsm + ((smb - (uint32_t)__cvta_generic_to_shared(dsm)) >> 2);
#pragma unroll
        for (int mt = 0; mt < 2; mt++)
#pragma unroll
            for (int half = 0; half < 2; half++) {
                int r = wm + mt * 16 + half * 8 + gid;
#pragma unroll
                for (int nt = 0; nt < 8; nt++) {
                    int c = wn + nt * 8 + tig * 2;
                    *(float2*)&sacc[r * 132 + c] =
                        make_float2(acc[mt][nt][half * 2 + 0],
                                    acc[mt][nt][half * 2 + 1]);
                }
            }
        __syncthreads();

        const int cl = lane * 4;
#pragma unroll 2
        for (int it = 0; it < 16; it++) {
            int el = it * 8 + warp;
            int er = m0 + el;
            if (er >= M) continue;
            int s_ = src[er], d_ = dst[er], b_ = batch[s_];
            float4 a = *(const float4*)&sacc[el * 132 + cl];
            float4 p1 = __ldg((const float4*)(g_p1 + (size_t)s_ * 256 + n0 + cl));
            float4 p2 = __ldg((const float4*)(g_p2 + (size_t)d_ * 256 + n0 + cl));
            float4 p4 = __ldg((const float4*)(g_p4 + (size_t)b_ * 256 + n0 + cl));
            float o0 = ssp(a.x + p1.x + p2.x + p4.x);
            float o1 = ssp(a.y + p1.y + p2.y + p4.y);
            float o2 = ssp(a.z + p1.z + p2.z + p4.z);
            float o3 = ssp(a.w + p1.w + p2.w + p4.w);
            red4(g_e2n + (size_t)d_ * 256 + n0 + cl, o0, o1, o2, o3);
            red4(g_small + OFF_E2G + b_ * 256 + n0 + cl, o0, o1, o2, o3);
            uint2 ov; ov.x = pack2(o0, o1); ov.y = pack2(o2, o3);
            *(uint2*)(g_bemid + (size_t)er * 256 + n0 + cl) = ov;
            if (lane == 0 && blockIdx.x == 0) {
                atomicAdd(&g_small[OFF_NCNT + d_], 1.0f);
                atomicAdd(&g_small[OFF_GCE + b_], 1.0f);
            }
        }
        if (SC == 5) {
            __syncthreads();
            if (tid == 0) {
                __threadfence();
                atomicAdd(&g_eflag[blockIdx.y], 1);
            }
        }
        return;
    }

    // ================= normal epilogue (also SC=5 z=1: out_e) =================
    int* sbt = (int*)dsm;
    if (SC == 2 || SC == 4) {
        if (tid < 128) sbt[tid] = batch[min(m0 + tid, M - 1)];
        __syncthreads();
    }

#pragma unroll
    for (int mt = 0; mt < 2; mt++) {
#pragma unroll
        for (int half = 0; half < 2; half++) {
            int r = wm + mt * 16 + half * 8 + gid;
            int gr = m0 + r;
            if (gr >= M) continue;
#pragma unroll
            for (int nt = 0; nt < 8; nt++) {
                int col = n0 + wn + nt * 8 + tig * 2;
                float o0 = acc[mt][nt][half * 2 + 0];
                float o1 = acc[mt][nt][half * 2 + 1];
                if (SC == 4) {
                    float2 q1v = *(const float2*)&R[(size_t)gr * 256 + col];
                    const float* q3f = (const float*)dst;
                    float2 q3v = *(const float2*)&q3f[(size_t)sbt[r] * 256 + col];
                    o0 = ssp(o0 + q1v.x + q3v.x);
                    o1 = ssp(o1 + q1v.y + q3v.y);
                    atomicAdd(&g_small[OFF_N2G + sbt[r] * 256 + col], o0);
                    atomicAdd(&g_small[OFF_N2G + sbt[r] * 256 + col + 1], o1);
                } else {
                    if (ACT) { o0 = ssp(o0); o1 = ssp(o1); }
                    if (SC == 2) {
                        atomicAdd(&g_small[OFF_N2G + sbt[r] * 256 + col], o0);
                        atomicAdd(&g_small[OFF_N2G + sbt[r] * 256 + col + 1], o1);
                    }
                    if (ADD) {
                        float2 rv = *(const float2*)&R[(size_t)gr * 256 + col];
                        o0 += rv.x; o1 += rv.y;
                    }
                }
                if (OUTBF) {
                    ((uint32_t*)Co)[((size_t)gr * 256 + col) >> 1] = pack2(o0, o1);
                } else {
                    *(float2*)&((float*)Co)[(size_t)gr * 256 + col] =
                        make_float2(o0, o1);
                }
            }
            if ((SC == 2 || SC == 4) && blockIdx.x == 0 && wn == 0 && tig == 0)
                atomicAdd(&g_small[OFF_GCN + sbt[r]], 1.0f);
        }
    }
}

// ---------------- glob_in = [n2g_mean, e2g_mean, g1] (bf16) ---------------------
__global__ __launch_bounds__(192) void build_glob_in()
{
    int gi = blockIdx.x;
    int t = threadIdx.x;
    int seg = t / 64, w = t % 64;
    uint2 val;
    if (seg == 0) {
        float inv = 1.0f / fmaxf(g_small[OFF_GCN + gi], 1.0f);
        float4 sv = *(const float4*)&g_small[OFF_N2G + gi * 256 + w * 4];
        val.x = pack2(sv.x * inv, sv.y * inv);
        val.y = pack2(sv.z * inv, sv.w * inv);
    } else if (seg == 1) {
        float inv = 1.0f / fmaxf(g_small[OFF_GCE + gi], 1.0f);
        float4 sv = *(const float4*)&g_small[OFF_E2G + gi * 256 + w * 4];
        val.x = pack2(sv.x * inv, sv.y * inv);
        val.y = pack2(sv.z * inv, sv.w * inv);
    } else {
        val = ((const uint2*)g_bg1)[(size_t)gi * 64 + w];
    }
    ((uint2*)g_bgin)[(size_t)gi * 192 + t] = val;
}

// ---------------- host side -------------------------------------------------------
template <typename T>
static T* sym(const void* symbol) {
    void* p = nullptr;
    cudaGetSymbolAddress(&p, symbol);
    return (T*)p;
}

typedef CUresult (*PFN_encode)(
    CUtensorMap*, CUtensorMapDataType, cuuint32_t, void*,
    const cuuint64_t*, const cuuint64_t*, const cuuint32_t*, const cuuint32_t*,
    CUtensorMapInterleave, CUtensorMapSwizzle, CUtensorMapL2promotion,
    CUtensorMapFloatOOBfill);

static void encB(PFN_encode fn, CUtensorMap* m, const void* base,
                 unsigned long long kElems, unsigned long long rows,
                 unsigned long long rowStrideBytes) {
    cuuint64_t dims[2] = {kElems, rows};
    cuuint64_t st[1] = {rowStrideBytes};
    cuuint32_t box[2] = {64u, 128u};
    cuuint32_t es[2] = {1u, 1u};
    fn(m, CU_TENSOR_MAP_DATA_TYPE_BFLOAT16, 2, (void*)base, dims, st, box, es,
       CU_TENSOR_MAP_INTERLEAVE_NONE, CU_TENSOR_MAP_SWIZZLE_128B,
       CU_TENSOR_MAP_L2_PROMOTION_L2_128B, CU_TENSOR_MAP_FLOAT_OOB_FILL_NONE);
}

extern "C" void kernel_launch(void* const* d_in, const int* in_sizes, int n_in,
                              void* d_out, int out_size) {
    const float* node_feats = (const float*)d_in[0];
    const float* edge_feats = (const float*)d_in[1];
    const float* glob_feats = (const float*)d_in[2];
    const int*   edge_index = (const int*)d_in[3];
    const int*   batch      = (const int*)d_in[4];

    const int* src = edge_index;
    const int* dst = edge_index + NE;

    float* out = (float*)d_out;
    float* out_n = out;
    float* out_e = out + (size_t)NN * 256;
    float* out_g = out + (size_t)(NN + NE) * 256;

    __nv_bfloat16* p_bnode = sym<__nv_bfloat16>(g_bnode);
    __nv_bfloat16* p_bedge = sym<__nv_bfloat16>(g_bedge);
    __nv_bfloat16* p_bglob = sym<__nv_bfloat16>(g_bglob);
    __nv_bfloat16* p_bn1   = sym<__nv_bfloat16>(g_bn1);
    __nv_bfloat16* p_be1   = sym<__nv_bfloat16>(g_be1);
    __nv_bfloat16* p_bg1   = sym<__nv_bfloat16>(g_bg1);
    __nv_bfloat16* p_bq2   = sym<__nv_bfloat16>(g_bq2);
    __nv_bfloat16* p_bgin  = sym<__nv_bfloat16>(g_bgin);
    __nv_bfloat16* p_bnmid = sym<__nv_bfloat16>(g_bnmid);
    __nv_bfloat16* p_bemid = sym<__nv_bfloat16>(g_bemid);
    __nv_bfloat16* p_bgmid = sym<__nv_bfloat16>(g_bgmid);
    __nv_bfloat16* p_wb    = sym<__nv_bfloat16>(g_wb);
    float* p_p1 = sym<float>(g_p1);
    float* p_p2 = sym<float>(g_p2);
    float* p_p4 = sym<float>(g_p4);
    float* p_q1 = sym<float>(g_q1);
    float* p_q3 = sym<float>(g_q3);
    float* p_e2n = sym<float>(g_e2n);
    float* p_small = sym<float>(g_small);
    float* p_eflag = sym<float>(g_eflag);

    PFN_encode encfn = nullptr;
    {
        void* fp = nullptr;
        cudaDriverEntryPointQueryResult qr;
        cudaGetDriverEntryPoint("cuTensorMapEncodeTiled", &fp,
                                cudaEnableDefault, &qr);
        encfn = (PFN_encode)fp;
    }

    static cudaStream_t sA = nullptr, sB = nullptr;
    static cudaEvent_t evStart, evRoot, evA, evQ1, evB, evQ3, evN, evA2;
    if (!sA) {
        cudaStreamCreateWithFlags(&sA, cudaStreamNonBlocking);
        cudaStreamCreateWithFlags(&sB, cudaStreamNonBlocking);
        cudaEventCreateWithFlags(&evStart, cudaEventDisableTiming);
        cudaEventCreateWithFlags(&evRoot, cudaEventDisableTiming);
        cudaEventCreateWithFlags(&evA, cudaEventDisableTiming);
        cudaEventCreateWithFlags(&evQ1, cudaEventDisableTiming);
        cudaEventCreateWithFlags(&evB, cudaEventDisableTiming);
        cudaEventCreateWithFlags(&evQ3, cudaEventDisableTiming);
        cudaEventCreateWithFlags(&evN, cudaEventDisableTiming);
        cudaEventCreateWithFlags(&evA2, cudaEventDisableTiming);
    }

    // ---- tensormaps
    CUtensorMap mA_node, mA_edge, mA_glob, mA_n1, mA_e1, mA_g1;
    CUtensorMap mA_q2, mA_gin, mA_nmid, mA_emid, mA_gmid;
    encB(encfn, &mA_node, p_bnode, 256, NN, 512);
    encB(encfn, &mA_edge, p_bedge, 256, NE, 512);
    encB(encfn, &mA_glob, p_bglob, 256, NG, 512);
    encB(encfn, &mA_n1, p_bn1, 256, NN, 512);
    encB(encfn, &mA_e1, p_be1, 256, NE, 512);
    encB(encfn, &mA_g1, p_bg1, 256, NG, 512);
    encB(encfn, &mA_q2, p_bq2, 256, NN, 512);
    encB(encfn, &mA_gin, p_bgin, 768, NG, 1536);
    encB(encfn, &mA_nmid, p_bnmid, 256, NN, 512);
    encB(encfn, &mA_emid, p_bemid, 256, NE, 512);
    encB(encfn, &mA_gmid, p_bgmid, 256, NG, 512);

    CUtensorMap mW_n1, mW_e1, mW_g1, mW_p1, mW_p2, mW_p3, mW_p4;
    CUtensorMap mW_nma, mW_nmb, mW_nmc, mW_gmlp, mW_n2, mW_e2, mW_g2;
    encB(encfn, &mW_n1, p_wb + WO0, 256, 256, 512);
    encB(encfn, &mW_e1, p_wb + WO1, 256, 256, 512);
    encB(encfn, &mW_g1, p_wb + WO2, 256, 256, 512);
    encB(encfn, &mW_p1, p_wb + WO3 + 0,   256, 256, 2048);
    encB(encfn, &mW_p2, p_wb + WO3 + 256, 256, 256, 2048);
    encB(encfn, &mW_p3, p_wb + WO3 + 512, 256, 256, 2048);
    encB(encfn, &mW_p4, p_wb + WO3 + 768, 256, 256, 2048);
    encB(encfn, &mW_nma, p_wb + WO4 + 0,   256, 256, 1536);
    encB(encfn, &mW_nmb, p_wb + WO4 + 256, 256, 256, 1536);
    encB(encfn, &mW_nmc, p_wb + WO4 + 512, 256, 256, 1536);
    encB(encfn, &mW_gmlp, p_wb + WO5, 768, 256, 1536);
    encB(encfn, &mW_n2, p_wb + WO6, 256, 256, 512);
    encB(encfn, &mW_e2, p_wb + WO7, 256, 256, 512);
    encB(encfn, &mW_g2, p_wb + WO8, 256, 256, 512);

    cudaFuncSetAttribute(gemm_b<1,0,1,0,0>, cudaFuncAttributeMaxDynamicSharedMemorySize, SMEMSZ);
    cudaFuncSetAttribute(gemm_b<0,0,0,0,0>, cudaFuncAttributeMaxDynamicSharedMemorySize, SMEMSZ);
    cudaFuncSetAttribute(gemm_b<0,0,0,0,1>, cudaFuncAttributeMaxDynamicSharedMemorySize, SMEMSZ);
    cudaFuncSetAttribute(gemm_b<1,1,0,5,0>, cudaFuncAttributeMaxDynamicSharedMemorySize, SMEMSZ);
    cudaFuncSetAttribute(gemm_b<1,0,1,4,0>, cudaFuncAttributeMaxDynamicSharedMemorySize, SMEMSZ);
    cudaFuncSetAttribute(gemm_b<1,1,0,0,0>, cudaFuncAttributeMaxDynamicSharedMemorySize, SMEMSZ);

    const int BN_N = (NN + 127) / 128;
    const int BN_E = (NE + 127) / 128;
    WSrc ws;
    for (int i = 0; i < 9; i++) ws.p[i] = (const float*)d_in[5 + i];

    cudaEventRecord(evStart, 0);

    // ---- stream B: weight rounding FIRST, then zeros + glob chain
    cudaStreamWaitEvent(sB, evStart, 0);
    round_weights<<<1024, 256, 0, sB>>>(ws);
    cudaEventRecord(evRoot, sB);
    zero_kernel<<<(NN * 256 + 255) / 256, 256, 0, sB>>>(p_e2n, NN * 256);
    zero_kernel<<<(SMALL_N + 255) / 256, 256, 0, sB>>>(p_small, SMALL_N);
    zero_kernel<<<7, 256, 0, sB>>>(p_eflag, 1568);
    convert_f2b<<<(NG * 32 + 255) / 256, 256, 0, sB>>>(glob_feats, p_bglob, NG * 32);
    gemm_b<1,0,1,0,0><<<dim3(2, 1), 256, SMEMSZ, sB>>>(mA_glob, mA_glob, mW_g1, mW_g1, nullptr, p_bg1, nullptr, NG, 256, nullptr, nullptr, nullptr);
    gemm_b<0,0,0,0,0><<<dim3(2, 1), 256, SMEMSZ, sB>>>(mA_g1, mA_g1, mW_p4, mW_p4, nullptr, p_p4, nullptr, NG, 256, nullptr, nullptr, nullptr);
    cudaEventRecord(evB, sB);
    gemm_b<0,0,0,0,0><<<dim3(2, 1), 256, SMEMSZ, sB>>>(mA_g1, mA_g1, mW_nmc, mW_nmc, nullptr, p_q3, nullptr, NG, 256, nullptr, nullptr, nullptr);
    cudaEventRecord(evQ3, sB);

    // ---- stream A: node chain (conv -> n1 -> P1P2(dual) -> Q1)
    cudaStreamWaitEvent(sA, evStart, 0);
    convert_f2b<<<(NN * 32 + 255) / 256, 256, 0, sA>>>(node_feats, p_bnode, NN * 32);
    cudaStreamWaitEvent(sA, evRoot, 0);
    gemm_b<1,0,1,0,0><<<dim3(2, BN_N), 256, SMEMSZ, sA>>>(mA_node, mA_node, mW_n1, mW_n1, nullptr, p_bn1, nullptr, NN, 256, nullptr, nullptr, nullptr);
    gemm_b<0,0,0,0,1><<<dim3(4, BN_N), 256, SMEMSZ, sA>>>(mA_n1, mA_n1, mW_p1, mW_p2, nullptr, p_p1, p_p2, NN, 256, nullptr, nullptr, nullptr);
    cudaEventRecord(evA, sA);
    gemm_b<0,0,0,0,0><<<dim3(2, BN_N), 256, SMEMSZ, sA>>>(mA_n1, mA_n1, mW_nma, mW_nma, nullptr, p_q1, nullptr, NN, 256, nullptr, nullptr, nullptr);
    cudaEventRecord(evQ1, sA);

    // ---- default stream: edge chain (conv -> e1 -> fused P3+combine+out_e)
    convert_f2b<<<(NE * 32 + 255) / 256, 256>>>(edge_feats, p_bedge, NE * 32);
    cudaStreamWaitEvent(0, evRoot, 0);
    gemm_b<1,0,1,0,0><<<dim3(2, BN_E), 256, SMEMSZ>>>(mA_edge, mA_edge, mW_e1, mW_e1, nullptr, p_be1, nullptr, NE, 256, nullptr, nullptr, nullptr);
    cudaStreamWaitEvent(0, evA, 0);
    cudaStreamWaitEvent(0, evB, 0);
    gemm_b<1,1,0,5,0><<<dim3(2, BN_E, 2), 256, SMEMSZ>>>(mA_e1, mA_emid, mW_p3, mW_e2, edge_feats, out_e, nullptr, NE, 256, src, dst, batch);

    // ---- default: node combine (conv e2n mean -> Q2 with fused combine)
    conv_e2n<<<(NN * 64 + 255) / 256, 256>>>();
    cudaStreamWaitEvent(0, evQ1, 0);
    cudaStreamWaitEvent(0, evQ3, 0);
    gemm_b<1,0,1,4,0><<<dim3(2, BN_N), 256, SMEMSZ>>>(mA_q2, mA_q2, mW_nmb, mW_nmb, p_q1, p_bnmid, nullptr, NN, 256, nullptr, (const int*)p_q3, batch);
    cudaEventRecord(evN, 0);

    // ---- stream A: out_n overlaps global model
    cudaStreamWaitEvent(sA, evN, 0);
    gemm_b<1,1,0,0,0><<<dim3(2, BN_N), 256, SMEMSZ, sA>>>(mA_nmid, mA_nmid, mW_n2, mW_n2, node_feats, out_n, nullptr, NN, 256, nullptr, nullptr, nullptr);
    cudaEventRecord(evA2, sA);

    // ---- default: global model + out_g
    build_glob_in<<<NG, 192>>>();
    gemm_b<1,0,1,0,0><<<dim3(2, 1), 256, SMEMSZ>>>(mA_gin, mA_gin, mW_gmlp, mW_gmlp, nullptr, p_bgmid, nullptr, NG, 768, nullptr, nullptr, nullptr);
    gemm_b<1,1,0,0,0><<<dim3(2, 1), 256, SMEMSZ>>>(mA_gmid, mA_gmid, mW_g2, mW_g2, glob_feats, out_g, nullptr, NG, 256, nullptr, nullptr, nullptr);

    // ---- rejoin side streams
    cudaStreamWaitEvent(0, evA2, 0);
}

// round 16
// speedup vs baseline: 1.0167x; 1.0167x over previous
#include <cuda_runtime.h>
#include <cuda.h>
#include <cuda_bf16.h>
#include <cstddef>
#include <cstdint>

#define NN 20000
#define NE 200000
#define NG 128

// ---------------- scratch (device globals) ----------------------------------
__device__ __align__(256) __nv_bfloat16 g_bnode[(size_t)NN * 256];
__device__ __align__(256) __nv_bfloat16 g_bedge[(size_t)NE * 256];
__device__ __align__(256) __nv_bfloat16 g_bglob[(size_t)NG * 256];
__device__ __align__(256) __nv_bfloat16 g_bn1[(size_t)NN * 256];
__device__ __align__(256) __nv_bfloat16 g_be1[(size_t)NE * 256];
__device__ __align__(256) __nv_bfloat16 g_bg1[(size_t)NG * 256];
__device__ __align__(256) __nv_bfloat16 g_bq2[(size_t)NN * 256];
__device__ __align__(256) __nv_bfloat16 g_bgin[(size_t)NG * 768];
__device__ __align__(256) __nv_bfloat16 g_bnmid[(size_t)NN * 256];
__device__ __align__(256) __nv_bfloat16 g_bemid[(size_t)NE * 256];
__device__ __align__(256) __nv_bfloat16 g_bgmid[(size_t)NG * 256];
__device__ __align__(256) __nv_bfloat16 g_wb[1048576];
__device__ __align__(256) float g_p1[(size_t)NN * 256];
__device__ __align__(256) float g_p2[(size_t)NN * 256];
__device__ __align__(256) float g_p4[(size_t)NG * 256];
__device__ __align__(256) float g_q1[(size_t)NN * 256];
__device__ __align__(256) float g_q3[(size_t)NG * 256];
__device__ __align__(256) float g_e2n[(size_t)NN * 256];
#define OFF_E2G 0
#define OFF_N2G 32768
#define OFF_NCNT 65536
#define OFF_GCE 85536
#define OFF_GCN 85664
#define SMALL_N 85792
__device__ float g_small[SMALL_N];

// ---------------- device helpers ---------------------------------------------
__device__ __forceinline__ float ssp(float x) {
    return fmaxf(x, 0.0f) + log1pf(__expf(-fabsf(x))) - 0.69314718055994531f;
}
__device__ __forceinline__ void mma_bf16(float* c,
    uint32_t a0, uint32_t a1, uint32_t a2, uint32_t a3,
    uint32_t b0, uint32_t b1)
{
    asm volatile(
        "mma.sync.aligned.m16n8k16.row.col.f32.bf16.bf16.f32 "
        "{%0,%1,%2,%3},{%4,%5,%6,%7},{%8,%9},{%0,%1,%2,%3};\n"
        : "+f"(c[0]), "+f"(c[1]), "+f"(c[2]), "+f"(c[3])
        : "r"(a0), "r"(a1), "r"(a2), "r"(a3), "r"(b0), "r"(b1));
}
__device__ __forceinline__ void ldsm4(uint32_t& r0, uint32_t& r1,
                                      uint32_t& r2, uint32_t& r3, uint32_t a) {
    asm volatile("ldmatrix.sync.aligned.m8n8.x4.shared.b16 {%0,%1,%2,%3},[%4];\n"
                 : "=r"(r0), "=r"(r1), "=r"(r2), "=r"(r3) : "r"(a));
}
__device__ __forceinline__ void red4(float* p, float a, float b, float c, float d) {
    asm volatile("red.global.add.v4.f32 [%0], {%1,%2,%3,%4};"
                 :: "l"(p), "f"(a), "f"(b), "f"(c), "f"(d) : "memory");
}
__device__ __forceinline__ void mbar_init(uint32_t mbar, uint32_t cnt) {
    asm volatile("mbarrier.init.shared.b64 [%0], %1;" :: "r"(mbar), "r"(cnt) : "memory");
}
__device__ __forceinline__ void mbar_expect(uint32_t mbar, uint32_t bytes) {
    asm volatile("mbarrier.arrive.expect_tx.shared.b64 _, [%0], %1;"
                 :: "r"(mbar), "r"(bytes) : "memory");
}
__device__ __forceinline__ void mbar_wait(uint32_t mbar, uint32_t parity) {
    asm volatile(
        "{\n\t.reg .pred P;\n\t"
        "W_%=:\n\t"
        "mbarrier.try_wait.parity.acquire.cta.shared::cta.b64 P, [%0], %1, 10000000;\n\t"
        "@P bra.uni D_%=;\n\t"
        "bra.uni W_%=;\n\t"
        "D_%=:\n\t}"
        :: "r"(mbar), "r"(parity) : "memory");
}
__device__ __forceinline__ void tma2d(uint32_t saddr, const CUtensorMap* tm,
                                      int cx, int cy, uint32_t mbar) {
    asm volatile(
        "cp.async.bulk.tensor.2d.shared::cta.global.tile.mbarrier::complete_tx::bytes "
        "[%0], [%1, {%2, %3}], [%4];"
        :: "r"(saddr), "l"(tm), "r"(cx), "r"(cy), "r"(mbar) : "memory");
}
__device__ __forceinline__ uint32_t pack2(float a, float b) {
    __nv_bfloat162 h = __floats2bfloat162_rn(a, b);
    return *(uint32_t*)&h;
}

// ---------------- zero fill ----------------------------------------------------
__global__ void zero_kernel(float* __restrict__ p, int n) {
    int i = blockIdx.x * blockDim.x + threadIdx.x;
    if (i < n) p[i] = 0.0f;
}

// ---------------- degree counts (off critical path) -----------------------------
__global__ __launch_bounds__(256) void count_kernel(
    const int* __restrict__ src, const int* __restrict__ dst,
    const int* __restrict__ batch)
{
    int i = blockIdx.x * 256 + threadIdx.x;
    if (i < NE) {
        atomicAdd(&g_small[OFF_NCNT + dst[i]], 1.0f);
        atomicAdd(&g_small[OFF_GCE + batch[src[i]]], 1.0f);
    } else if (i < NE + NN) {
        atomicAdd(&g_small[OFF_GCN + batch[i - NE]], 1.0f);
    }
}

// ---------------- fp32 -> bf16 conversion (8 floats / thread) -------------------
__global__ __launch_bounds__(256) void convert_f2b(
    const float* __restrict__ src, __nv_bfloat16* __restrict__ dst, int n8)
{
    int i = blockIdx.x * 256 + threadIdx.x;
    if (i >= n8) return;
    float4 a = ((const float4*)src)[i * 2];
    float4 b = ((const float4*)src)[i * 2 + 1];
    uint4 o;
    o.x = pack2(a.x, a.y);
    o.y = pack2(a.z, a.w);
    o.z = pack2(b.x, b.y);
    o.w = pack2(b.z, b.w);
    ((uint4*)dst)[i] = o;
}

// ---------------- e2n mean -> bf16 ------------------------------------------------
__global__ __launch_bounds__(256) void conv_e2n()
{
    int i = blockIdx.x * 256 + threadIdx.x;
    if (i >= NN * 64) return;
    int v = i >> 6;
    float inv = 1.0f / fmaxf(g_small[OFF_NCNT + v], 1.0f);
    float4 sv = ((const float4*)g_e2n)[i];
    uint2 o;
    o.x = pack2(sv.x * inv, sv.y * inv);
    o.y = pack2(sv.z * inv, sv.w * inv);
    ((uint2*)g_bq2)[i] = o;
}

// ---------------- convert all weights to bf16 ------------------------------------
struct WSrc { const float* p[9]; };
#define WO0 0
#define WO1 65536
#define WO2 131072
#define WO3 196608
#define WO4 458752
#define WO5 655360
#define WO6 851968
#define WO7 917504
#define WO8 983040
__global__ __launch_bounds__(256) void round_weights(WSrc ws) {
    int f = (blockIdx.x * 256 + threadIdx.x) * 4;
    if (f >= 1048576) return;
    const float* sp; int base;
    if      (f < WO1) { sp = ws.p[0]; base = WO0; }
    else if (f < WO2) { sp = ws.p[1]; base = WO1; }
    else if (f < WO3) { sp = ws.p[2]; base = WO2; }
    else if (f < WO4) { sp = ws.p[3]; base = WO3; }
    else if (f < WO5) { sp = ws.p[4]; base = WO4; }
    else if (f < WO6) { sp = ws.p[5]; base = WO5; }
    else if (f < WO7) { sp = ws.p[6]; base = WO6; }
    else if (f < WO8) { sp = ws.p[7]; base = WO7; }
    else              { sp = ws.p[8]; base = WO8; }
    float4 v = *(const float4*)(sp + (f - base));
    uint2 o;
    o.x = pack2(v.x, v.y);
    o.y = pack2(v.z, v.w);
    *(uint2*)(g_wb + f) = o;
}

// ---------------- TMA-fed bf16 GEMM ----------------------------------------------
// C[M,256] = [ssp](A[M,K] @ W^T) [+R]. Block 128x128, 8 warps, warp tile 32x64,
// TBK=64 bf16 (128B rows, SW128), 3-stage TMA pipe.
// DUAL: grid.x=4 selects (tmW,Cout)/(tmW2,Cout2).
// SC=3: fused edge combine (counts precomputed elsewhere).
// SC=4: fused node combine: o=ssp(acc + R[row] + Q3[batch[row]]), n2g scatter.
#define STG_BYTES 32768u
#define SMEMSZ (3 * 32768 + 1024)

template <int ACT, int ADD, int OUTBF, int SC, int DUAL>
__global__ __launch_bounds__(256, 2) void gemm_b(
    const __grid_constant__ CUtensorMap tmA,
    const __grid_constant__ CUtensorMap tmW,
    const __grid_constant__ CUtensorMap tmW2,
    const float* __restrict__ R, void* __restrict__ Cout, void* __restrict__ Cout2,
    int M, int K,
    const int* __restrict__ src, const int* __restrict__ dst,
    const int* __restrict__ batch)
{
    extern __shared__ float dsm[];
    __shared__ __align__(8) uint64_t mbar_s[3];
    uint32_t smb = (uint32_t)__cvta_generic_to_shared(dsm);
    smb = (smb + 1023u) & ~1023u;
    const uint32_t mb = (uint32_t)__cvta_generic_to_shared(mbar_s);

    const int tid = threadIdx.x;
    const int m0 = blockIdx.y * 128;
    const int halfW = DUAL ? (int)(blockIdx.x >> 1) : 0;
    const int n0 = DUAL ? (int)(blockIdx.x & 1) * 128 : (int)blockIdx.x * 128;
    void* Co = (DUAL && halfW) ? Cout2 : Cout;
    const CUtensorMap* wmap = (DUAL && halfW) ? &tmW2 : &tmW;

    if (tid == 0) {
        mbar_init(mb, 1); mbar_init(mb + 8, 1); mbar_init(mb + 16, 1);
    }
    __syncthreads();

    const int KT = K / 64;
    auto issue = [&](int kt, int s) {
        uint32_t base = smb + (uint32_t)s * STG_BYTES;
        mbar_expect(mb + s * 8, STG_BYTES);
        tma2d(base, &tmA, kt * 64, m0, mb + s * 8);
        tma2d(base + 16384u, wmap, kt * 64, n0, mb + s * 8);
    };
    if (tid == 0) {
        int pre = KT < 3 ? KT : 3;
        for (int i = 0; i < pre; i++) issue(i, i);
    }

    const int lane = tid & 31, warp = tid >> 5;
    const int wm = (warp & 3) * 32;
    const int wn = (warp >> 2) * 64;
    const int gid = lane >> 2, tig = lane & 3;
    const int hA = (lane >> 4) & 1;
    const int hB = (lane >> 3) & 1;
    const int arow = wm + (lane & 15);
    const int brow = wn + ((lane >> 4) & 1) * 8 + (lane & 7);
    const uint32_t aAddr = smb + (uint32_t)(arow * 128);
    const uint32_t bAddr = smb + 16384u + (uint32_t)(brow * 128);
    uint32_t cA[4], cB[4];
#pragma unroll
    for (int ks = 0; ks < 4; ks++) {
        cA[ks] = (uint32_t)(((ks * 2 + hA) ^ (arow & 7)) << 4);
        cB[ks] = (uint32_t)(((ks * 2 + hB) ^ (brow & 7)) << 4);
    }

    float acc[2][8][4];
#pragma unroll
    for (int mt = 0; mt < 2; mt++)
#pragma unroll
        for (int nt = 0; nt < 8; nt++)
#pragma unroll
            for (int i = 0; i < 4; i++) acc[mt][nt][i] = 0.0f;

    for (int kt = 0; kt < KT; kt++) {
        const int s = kt % 3;
        mbar_wait(mb + s * 8, (uint32_t)((kt / 3) & 1));
        const uint32_t so = (uint32_t)s * STG_BYTES;

#pragma unroll
        for (int ks = 0; ks < 4; ks++) {
            uint32_t a[2][4];
#pragma unroll
            for (int mt = 0; mt < 2; mt++)
                ldsm4(a[mt][0], a[mt][1], a[mt][2], a[mt][3],
                      aAddr + so + (uint32_t)(mt * 2048) + cA[ks]);
            uint32_t b0[8], b1[8];
#pragma unroll
            for (int g = 0; g < 4; g++)
                ldsm4(b0[2 * g], b1[2 * g], b0[2 * g + 1], b1[2 * g + 1],
                      bAddr + so + (uint32_t)(g * 2048) + cB[ks]);
#pragma unroll
            for (int mt = 0; mt < 2; mt++)
#pragma unroll
                for (int nt = 0; nt < 8; nt++)
                    mma_bf16(acc[mt][nt], a[mt][0], a[mt][1], a[mt][2],
                             a[mt][3], b0[nt], b1[nt]);
        }
        __syncthreads();
        if (tid == 0 && kt + 3 < KT) issue(kt + 3, s);
    }

    // ================= SC=3: fused edge combine (warp-per-edge) =================
    if (SC == 3) {
        float* sacc = dsm + ((smb - (uint32_t)__cvta_generic_to_shared(dsm)) >> 2);
#pragma unroll
        for (int mt = 0; mt < 2; mt++)
#pragma unroll
            for (int half = 0; half < 2; half++) {
                int r = wm + mt * 16 + half * 8 + gid;
#pragma unroll
                for (int nt = 0; nt < 8; nt++) {
                    int c = wn + nt * 8 + tig * 2;
                    *(float2*)&sacc[r * 132 + c] =
                        make_float2(acc[mt][nt][half * 2 + 0],
                                    acc[mt][nt][half * 2 + 1]);
                }
            }
        __syncthreads();

        const int cl = lane * 4;
#pragma unroll 2
        for (int it = 0; it < 16; it++) {
            int el = it * 8 + warp;
            int er = m0 + el;
            if (er >= M) continue;
            int s_ = src[er], d_ = dst[er], b_ = batch[s_];
            float4 a = *(const float4*)&sacc[el * 132 + cl];
            float4 p1 = __ldg((const float4*)(g_p1 + (size_t)s_ * 256 + n0 + cl));
            float4 p2 = __ldg((const float4*)(g_p2 + (size_t)d_ * 256 + n0 + cl));
            float4 p4 = __ldg((const float4*)(g_p4 + (size_t)b_ * 256 + n0 + cl));
            float o0 = ssp(a.x + p1.x + p2.x + p4.x);
            float o1 = ssp(a.y + p1.y + p2.y + p4.y);
            float o2 = ssp(a.z + p1.z + p2.z + p4.z);
            float o3 = ssp(a.w + p1.w + p2.w + p4.w);
            red4(g_e2n + (size_t)d_ * 256 + n0 + cl, o0, o1, o2, o3);
            red4(g_small + OFF_E2G + b_ * 256 + n0 + cl, o0, o1, o2, o3);
            uint2 ov; ov.x = pack2(o0, o1); ov.y = pack2(o2, o3);
            *(uint2*)(g_bemid + (size_t)er * 256 + n0 + cl) = ov;
        }
        return;
    }

    // ================= normal epilogue =================
    int* sbt = (int*)dsm;
    if (SC == 4) {
        if (tid < 128) sbt[tid] = batch[min(m0 + tid, M - 1)];
        __syncthreads();
    }

#pragma unroll
    for (int mt = 0; mt < 2; mt++) {
#pragma unroll
        for (int half = 0; half < 2; half++) {
            int r = wm + mt * 16 + half * 8 + gid;
            int gr = m0 + r;
            if (gr >= M) continue;
#pragma unroll
            for (int nt = 0; nt < 8; nt++) {
                int col = n0 + wn + nt * 8 + tig * 2;
                float o0 = acc[mt][nt][half * 2 + 0];
                float o1 = acc[mt][nt][half * 2 + 1];
                if (SC == 4) {
                    float2 q1v = *(const float2*)&R[(size_t)gr * 256 + col];
                    const float* q3f = (const float*)dst;
                    float2 q3v = *(const float2*)&q3f[(size_t)sbt[r] * 256 + col];
                    o0 = ssp(o0 + q1v.x + q3v.x);
                    o1 = ssp(o1 + q1v.y + q3v.y);
                    atomicAdd(&g_small[OFF_N2G + sbt[r] * 256 + col], o0);
                    atomicAdd(&g_small[OFF_N2G + sbt[r] * 256 + col + 1], o1);
                } else {
                    if (ACT) { o0 = ssp(o0); o1 = ssp(o1); }
                    if (ADD) {
                        float2 rv = *(const float2*)&R[(size_t)gr * 256 + col];
                        o0 += rv.x; o1 += rv.y;
                    }
                }
                if (OUTBF) {
                    ((uint32_t*)Co)[((size_t)gr * 256 + col) >> 1] = pack2(o0, o1);
                } else {
                    *(float2*)&((float*)Co)[(size_t)gr * 256 + col] =
                        make_float2(o0, o1);
                }
            }
        }
    }
}

// ---------------- glob_in = [n2g_mean, e2g_mean, g1] (bf16) ---------------------
__global__ __launch_bounds__(192) void build_glob_in()
{
    int gi = blockIdx.x;
    int t = threadIdx.x;
    int seg = t / 64, w = t % 64;
    uint2 val;
    if (seg == 0) {
        float inv = 1.0f / fmaxf(g_small[OFF_GCN + gi], 1.0f);
        float4 sv = *(const float4*)&g_small[OFF_N2G + gi * 256 + w * 4];
        val.x = pack2(sv.x * inv, sv.y * inv);
        val.y = pack2(sv.z * inv, sv.w * inv);
    } else if (seg == 1) {
        float inv = 1.0f / fmaxf(g_small[OFF_GCE + gi], 1.0f);
        float4 sv = *(const float4*)&g_small[OFF_E2G + gi * 256 + w * 4];
        val.x = pack2(sv.x * inv, sv.y * inv);
        val.y = pack2(sv.z * inv, sv.w * inv);
    } else {
        val = ((const uint2*)g_bg1)[(size_t)gi * 64 + w];
    }
    ((uint2*)g_bgin)[(size_t)gi * 192 + t] = val;
}

// ---------------- host side -------------------------------------------------------
template <typename T>
static T* sym(const void* symbol) {
    void* p = nullptr;
    cudaGetSymbolAddress(&p, symbol);
    return (T*)p;
}

typedef CUresult (*PFN_encode)(
    CUtensorMap*, CUtensorMapDataType, cuuint32_t, void*,
    const cuuint64_t*, const cuuint64_t*, const cuuint32_t*, const cuuint32_t*,
    CUtensorMapInterleave, CUtensorMapSwizzle, CUtensorMapL2promotion,
    CUtensorMapFloatOOBfill);

static void encB(PFN_encode fn, CUtensorMap* m, const void* base,
                 unsigned long long kElems, unsigned long long rows,
                 unsigned long long rowStrideBytes) {
    cuuint64_t dims[2] = {kElems, rows};
    cuuint64_t st[1] = {rowStrideBytes};
    cuuint32_t box[2] = {64u, 128u};
    cuuint32_t es[2] = {1u, 1u};
    fn(m, CU_TENSOR_MAP_DATA_TYPE_BFLOAT16, 2, (void*)base, dims, st, box, es,
       CU_TENSOR_MAP_INTERLEAVE_NONE, CU_TENSOR_MAP_SWIZZLE_128B,
       CU_TENSOR_MAP_L2_PROMOTION_L2_128B, CU_TENSOR_MAP_FLOAT_OOB_FILL_NONE);
}

extern "C" void kernel_launch(void* const* d_in, const int* in_sizes, int n_in,
                              void* d_out, int out_size) {
    const float* node_feats = (const float*)d_in[0];
    const float* edge_feats = (const float*)d_in[1];
    const float* glob_feats = (const float*)d_in[2];
    const int*   edge_index = (const int*)d_in[3];
    const int*   batch      = (const int*)d_in[4];

    const int* src = edge_index;
    const int* dst = edge_index + NE;

    float* out = (float*)d_out;
    float* out_n = out;
    float* out_e = out + (size_t)NN * 256;
    float* out_g = out + (size_t)(NN + NE) * 256;

    __nv_bfloat16* p_bnode = sym<__nv_bfloat16>(g_bnode);
    __nv_bfloat16* p_bedge = sym<__nv_bfloat16>(g_bedge);
    __nv_bfloat16* p_bglob = sym<__nv_bfloat16>(g_bglob);
    __nv_bfloat16* p_bn1   = sym<__nv_bfloat16>(g_bn1);
    __nv_bfloat16* p_be1   = sym<__nv_bfloat16>(g_be1);
    __nv_bfloat16* p_bg1   = sym<__nv_bfloat16>(g_bg1);
    __nv_bfloat16* p_bq2   = sym<__nv_bfloat16>(g_bq2);
    __nv_bfloat16* p_bgin  = sym<__nv_bfloat16>(g_bgin);
    __nv_bfloat16* p_bnmid = sym<__nv_bfloat16>(g_bnmid);
    __nv_bfloat16* p_bemid = sym<__nv_bfloat16>(g_bemid);
    __nv_bfloat16* p_bgmid = sym<__nv_bfloat16>(g_bgmid);
    __nv_bfloat16* p_wb    = sym<__nv_bfloat16>(g_wb);
    float* p_p1 = sym<float>(g_p1);
    float* p_p2 = sym<float>(g_p2);
    float* p_p4 = sym<float>(g_p4);
    float* p_q1 = sym<float>(g_q1);
    float* p_q3 = sym<float>(g_q3);
    float* p_e2n = sym<float>(g_e2n);
    float* p_small = sym<float>(g_small);

    PFN_encode encfn = nullptr;
    {
        void* fp = nullptr;
        cudaDriverEntryPointQueryResult qr;
        cudaGetDriverEntryPoint("cuTensorMapEncodeTiled", &fp,
                                cudaEnableDefault, &qr);
        encfn = (PFN_encode)fp;
    }

    static cudaStream_t sA = nullptr, sB = nullptr, sC = nullptr;
    static cudaEvent_t evStart, evRoot, evA, evQ1, evB, evQ3, evP3, evC, evN, evA2;
    if (!sA) {
        cudaStreamCreateWithFlags(&sA, cudaStreamNonBlocking);
        cudaStreamCreateWithFlags(&sB, cudaStreamNonBlocking);
        cudaStreamCreateWithFlags(&sC, cudaStreamNonBlocking);
        cudaEventCreateWithFlags(&evStart, cudaEventDisableTiming);
        cudaEventCreateWithFlags(&evRoot, cudaEventDisableTiming);
        cudaEventCreateWithFlags(&evA, cudaEventDisableTiming);
        cudaEventCreateWithFlags(&evQ1, cudaEventDisableTiming);
        cudaEventCreateWithFlags(&evB, cudaEventDisableTiming);
        cudaEventCreateWithFlags(&evQ3, cudaEventDisableTiming);
        cudaEventCreateWithFlags(&evP3, cudaEventDisableTiming);
        cudaEventCreateWithFlags(&evC, cudaEventDisableTiming);
        cudaEventCreateWithFlags(&evN, cudaEventDisableTiming);
        cudaEventCreateWithFlags(&evA2, cudaEventDisableTiming);
    }

    // ---- tensormaps
    CUtensorMap mA_node, mA_edge, mA_glob, mA_n1, mA_e1, mA_g1;
    CUtensorMap mA_q2, mA_gin, mA_nmid, mA_emid, mA_gmid;
    encB(encfn, &mA_node, p_bnode, 256, NN, 512);
    encB(encfn, &mA_edge, p_bedge, 256, NE, 512);
    encB(encfn, &mA_glob, p_bglob, 256, NG, 512);
    encB(encfn, &mA_n1, p_bn1, 256, NN, 512);
    encB(encfn, &mA_e1, p_be1, 256, NE, 512);
    encB(encfn, &mA_g1, p_bg1, 256, NG, 512);
    encB(encfn, &mA_q2, p_bq2, 256, NN, 512);
    encB(encfn, &mA_gin, p_bgin, 768, NG, 1536);
    encB(encfn, &mA_nmid, p_bnmid, 256, NN, 512);
    encB(encfn, &mA_emid, p_bemid, 256, NE, 512);
    encB(encfn, &mA_gmid, p_bgmid, 256, NG, 512);

    CUtensorMap mW_n1, mW_e1, mW_g1, mW_p1, mW_p2, mW_p3, mW_p4;
    CUtensorMap mW_nma, mW_nmb, mW_nmc, mW_gmlp, mW_n2, mW_e2, mW_g2;
    encB(encfn, &mW_n1, p_wb + WO0, 256, 256, 512);
    encB(encfn, &mW_e1, p_wb + WO1, 256, 256, 512);
    encB(encfn, &mW_g1, p_wb + WO2, 256, 256, 512);
    encB(encfn, &mW_p1, p_wb + WO3 + 0,   256, 256, 2048);
    encB(encfn, &mW_p2, p_wb + WO3 + 256, 256, 256, 2048);
    encB(encfn, &mW_p3, p_wb + WO3 + 512, 256, 256, 2048);
    encB(encfn, &mW_p4, p_wb + WO3 + 768, 256, 256, 2048);
    encB(encfn, &mW_nma, p_wb + WO4 + 0,   256, 256, 1536);
    encB(encfn, &mW_nmb, p_wb + WO4 + 256, 256, 256, 1536);
    encB(encfn, &mW_nmc, p_wb + WO4 + 512, 256, 256, 1536);
    encB(encfn, &mW_gmlp, p_wb + WO5, 768, 256, 1536);
    encB(encfn, &mW_n2, p_wb + WO6, 256, 256, 512);
    encB(encfn, &mW_e2, p_wb + WO7, 256, 256, 512);
    encB(encfn, &mW_g2, p_wb + WO8, 256, 256, 512);

    cudaFuncSetAttribute(gemm_b<1,0,1,0,0>, cudaFuncAttributeMaxDynamicSharedMemorySize, SMEMSZ);
    cudaFuncSetAttribute(gemm_b<0,0,0,0,0>, cudaFuncAttributeMaxDynamicSharedMemorySize, SMEMSZ);
    cudaFuncSetAttribute(gemm_b<0,0,0,0,1>, cudaFuncAttributeMaxDynamicSharedMemorySize, SMEMSZ);
    cudaFuncSetAttribute(gemm_b<0,0,0,3,0>, cudaFuncAttributeMaxDynamicSharedMemorySize, SMEMSZ);
    cudaFuncSetAttribute(gemm_b<1,0,1,4,0>, cudaFuncAttributeMaxDynamicSharedMemorySize, SMEMSZ);
    cudaFuncSetAttribute(gemm_b<1,1,0,0,0>, cudaFuncAttributeMaxDynamicSharedMemorySize, SMEMSZ);

    const int BN_N = (NN + 127) / 128;
    const int BN_E = (NE + 127) / 128;
    WSrc ws;
    for (int i = 0; i < 9; i++) ws.p[i] = (const float*)d_in[5 + i];

    cudaEventRecord(evStart, 0);

    // ---- stream B: weight rounding FIRST, then zeros + counts + glob chain
    cudaStreamWaitEvent(sB, evStart, 0);
    round_weights<<<1024, 256, 0, sB>>>(ws);
    cudaEventRecord(evRoot, sB);
    zero_kernel<<<(NN * 256 + 255) / 256, 256, 0, sB>>>(p_e2n, NN * 256);
    zero_kernel<<<(SMALL_N + 255) / 256, 256, 0, sB>>>(p_small, SMALL_N);
    count_kernel<<<(NE + NN + 255) / 256, 256, 0, sB>>>(src, dst, batch);
    convert_f2b<<<(NG * 32 + 255) / 256, 256, 0, sB>>>(glob_feats, p_bglob, NG * 32);
    gemm_b<1,0,1,0,0><<<dim3(2, 1), 256, SMEMSZ, sB>>>(mA_glob, mW_g1, mW_g1, nullptr, p_bg1, nullptr, NG, 256, nullptr, nullptr, nullptr);
    gemm_b<0,0,0,0,1><<<dim3(4, 1), 256, SMEMSZ, sB>>>(mA_g1, mW_p4, mW_nmc, nullptr, p_p4, p_q3, NG, 256, nullptr, nullptr, nullptr);
    cudaEventRecord(evB, sB);
    cudaEventRecord(evQ3, sB);

    // ---- stream A: node chain (conv -> n1 -> P1P2(dual) -> Q1)
    cudaStreamWaitEvent(sA, evStart, 0);
    convert_f2b<<<(NN * 32 + 255) / 256, 256, 0, sA>>>(node_feats, p_bnode, NN * 32);
    cudaStreamWaitEvent(sA, evRoot, 0);
    gemm_b<1,0,1,0,0><<<dim3(2, BN_N), 256, SMEMSZ, sA>>>(mA_node, mW_n1, mW_n1, nullptr, p_bn1, nullptr, NN, 256, nullptr, nullptr, nullptr);
    gemm_b<0,0,0,0,1><<<dim3(4, BN_N), 256, SMEMSZ, sA>>>(mA_n1, mW_p1, mW_p2, nullptr, p_p1, p_p2, NN, 256, nullptr, nullptr, nullptr);
    cudaEventRecord(evA, sA);
    gemm_b<0,0,0,0,0><<<dim3(2, BN_N), 256, SMEMSZ, sA>>>(mA_n1, mW_nma, mW_nma, nullptr, p_q1, nullptr, NN, 256, nullptr, nullptr, nullptr);
    cudaEventRecord(evQ1, sA);

    // ---- default stream: edge chain (conv -> e1 -> P3+combine)
    convert_f2b<<<(NE * 32 + 255) / 256, 256>>>(edge_feats, p_bedge, NE * 32);
    cudaStreamWaitEvent(0, evRoot, 0);
    gemm_b<1,0,1,0,0><<<dim3(2, BN_E), 256, SMEMSZ>>>(mA_edge, mW_e1, mW_e1, nullptr, p_be1, nullptr, NE, 256, nullptr, nullptr, nullptr);
    cudaStreamWaitEvent(0, evA, 0);
    cudaStreamWaitEvent(0, evB, 0);
    gemm_b<0,0,0,3,0><<<dim3(2, BN_E), 256, SMEMSZ>>>(mA_e1, mW_p3, mW_p3, nullptr, p_bemid, nullptr, NE, 256, src, dst, batch);
    cudaEventRecord(evP3, 0);

    // ---- stream C: out_e (needs only emid)
    cudaStreamWaitEvent(sC, evP3, 0);
    gemm_b<1,1,0,0,0><<<dim3(2, BN_E), 256, SMEMSZ, sC>>>(mA_emid, mW_e2, mW_e2, edge_feats, out_e, nullptr, NE, 256, nullptr, nullptr, nullptr);
    cudaEventRecord(evC, sC);

    // ---- default: node combine (conv e2n mean -> Q2 with fused combine)
    conv_e2n<<<(NN * 64 + 255) / 256, 256>>>();
    cudaStreamWaitEvent(0, evQ1, 0);
    cudaStreamWaitEvent(0, evQ3, 0);
    gemm_b<1,0,1,4,0><<<dim3(2, BN_N), 256, SMEMSZ>>>(mA_q2, mW_nmb, mW_nmb, p_q1, p_bnmid, nullptr, NN, 256, nullptr, (const int*)p_q3, batch);
    cudaEventRecord(evN, 0);

    // ---- stream A: out_n overlaps global model
    cudaStreamWaitEvent(sA, evN, 0);
    gemm_b<1,1,0,0,0><<<dim3(2, BN_N), 256, SMEMSZ, sA>>>(mA_nmid, mW_n2, mW_n2, node_feats, out_n, nullptr, NN, 256, nullptr, nullptr, nullptr);
    cudaEventRecord(evA2, sA);

    // ---- default: global model + out_g
    build_glob_in<<<NG, 192>>>();
    gemm_b<1,0,1,0,0><<<dim3(2, 1), 256, SMEMSZ>>>(mA_gin, mW_gmlp, mW_gmlp, nullptr, p_bgmid, nullptr, NG, 768, nullptr, nullptr, nullptr);
    gemm_b<1,1,0,0,0><<<dim3(2, 1), 256, SMEMSZ>>>(mA_gmid, mW_g2, mW_g2, glob_feats, out_g, nullptr, NG, 256, nullptr, nullptr, nullptr);

    // ---- rejoin side streams
    cudaStreamWaitEvent(0, evC, 0);
    cudaStreamWaitEvent(0, evA2, 0);
}

// round 17
// speedup vs baseline: 1.0699x; 1.0523x over previous
#include <cuda_runtime.h>
#include <cuda.h>
#include <cuda_bf16.h>
#include <cstddef>
#include <cstdint>

#define NN 20000
#define NE 200000
#define NG 128

// ---------------- scratch (device globals) ----------------------------------
__device__ __align__(256) __nv_bfloat16 g_bnode[(size_t)NN * 256];
__device__ __align__(256) __nv_bfloat16 g_bedge[(size_t)NE * 256];
__device__ __align__(256) __nv_bfloat16 g_bglob[(size_t)NG * 256];
__device__ __align__(256) __nv_bfloat16 g_bn1[(size_t)NN * 256];
__device__ __align__(256) __nv_bfloat16 g_be1[(size_t)NE * 256];
__device__ __align__(256) __nv_bfloat16 g_bg1[(size_t)NG * 256];
__device__ __align__(256) __nv_bfloat16 g_bq2[(size_t)NN * 256];
__device__ __align__(256) __nv_bfloat16 g_bgin[(size_t)NG * 768];
__device__ __align__(256) __nv_bfloat16 g_bnmid[(size_t)NN * 256];
__device__ __align__(256) __nv_bfloat16 g_bemid[(size_t)NE * 256];
__device__ __align__(256) __nv_bfloat16 g_bgmid[(size_t)NG * 256];
__device__ __align__(256) __nv_bfloat16 g_wb[1048576];
__device__ __align__(256) float g_p1[(size_t)NN * 256];
__device__ __align__(256) float g_p2[(size_t)NN * 256];
__device__ __align__(256) float g_p4[(size_t)NG * 256];
__device__ __align__(256) float g_q1[(size_t)NN * 256];
__device__ __align__(256) float g_q3[(size_t)NG * 256];
__device__ __align__(256) float g_e2n[(size_t)NN * 256];
#define OFF_E2G 0
#define OFF_N2G 32768
#define OFF_NCNT 65536
#define OFF_GCE 85536
#define OFF_GCN 85664
#define SMALL_N 85792
__device__ float g_small[SMALL_N];

// ---------------- device helpers ---------------------------------------------
__device__ __forceinline__ float ssp(float x) {
    return fmaxf(x, 0.0f) + log1pf(__expf(-fabsf(x))) - 0.69314718055994531f;
}
__device__ __forceinline__ void mma_bf16(float* c,
    uint32_t a0, uint32_t a1, uint32_t a2, uint32_t a3,
    uint32_t b0, uint32_t b1)
{
    asm volatile(
        "mma.sync.aligned.m16n8k16.row.col.f32.bf16.bf16.f32 "
        "{%0,%1,%2,%3},{%4,%5,%6,%7},{%8,%9},{%0,%1,%2,%3};\n"
        : "+f"(c[0]), "+f"(c[1]), "+f"(c[2]), "+f"(c[3])
        : "r"(a0), "r"(a1), "r"(a2), "r"(a3), "r"(b0), "r"(b1));
}
__device__ __forceinline__ void ldsm4(uint32_t& r0, uint32_t& r1,
                                      uint32_t& r2, uint32_t& r3, uint32_t a) {
    asm volatile("ldmatrix.sync.aligned.m8n8.x4.shared.b16 {%0,%1,%2,%3},[%4];\n"
                 : "=r"(r0), "=r"(r1), "=r"(r2), "=r"(r3) : "r"(a));
}
__device__ __forceinline__ void red4(float* p, float a, float b, float c, float d) {
    asm volatile("red.global.add.v4.f32 [%0], {%1,%2,%3,%4};"
                 :: "l"(p), "f"(a), "f"(b), "f"(c), "f"(d) : "memory");
}
__device__ __forceinline__ void mbar_init(uint32_t mbar, uint32_t cnt) {
    asm volatile("mbarrier.init.shared.b64 [%0], %1;" :: "r"(mbar), "r"(cnt) : "memory");
}
__device__ __forceinline__ void mbar_expect(uint32_t mbar, uint32_t bytes) {
    asm volatile("mbarrier.arrive.expect_tx.shared.b64 _, [%0], %1;"
                 :: "r"(mbar), "r"(bytes) : "memory");
}
__device__ __forceinline__ void mbar_wait(uint32_t mbar, uint32_t parity) {
    asm volatile(
        "{\n\t.reg .pred P;\n\t"
        "W_%=:\n\t"
        "mbarrier.try_wait.parity.acquire.cta.shared::cta.b64 P, [%0], %1, 10000000;\n\t"
        "@P bra.uni D_%=;\n\t"
        "bra.uni W_%=;\n\t"
        "D_%=:\n\t}"
        :: "r"(mbar), "r"(parity) : "memory");
}
__device__ __forceinline__ void tma2d(uint32_t saddr, const CUtensorMap* tm,
                                      int cx, int cy, uint32_t mbar) {
    asm volatile(
        "cp.async.bulk.tensor.2d.shared::cta.global.tile.mbarrier::complete_tx::bytes "
        "[%0], [%1, {%2, %3}], [%4];"
        :: "r"(saddr), "l"(tm), "r"(cx), "r"(cy), "r"(mbar) : "memory");
}
__device__ __forceinline__ uint32_t pack2(float a, float b) {
    __nv_bfloat162 h = __floats2bfloat162_rn(a, b);
    return *(uint32_t*)&h;
}

// ---------------- zero fill ----------------------------------------------------
__global__ void zero_kernel(float* __restrict__ p, int n) {
    int i = blockIdx.x * blockDim.x + threadIdx.x;
    if (i < n) p[i] = 0.0f;
}

// ---------------- degree counts (smem-aggregated, off critical path) ------------
__global__ __launch_bounds__(256) void count_kernel(
    const int* __restrict__ src, const int* __restrict__ dst,
    const int* __restrict__ batch)
{
    __shared__ float binsE[128];
    __shared__ float binsN[128];
    int t = threadIdx.x;
    if (t < 128) { binsE[t] = 0.0f; binsN[t] = 0.0f; }
    __syncthreads();
    int i = blockIdx.x * 256 + t;
    if (i < NE) {
        atomicAdd(&g_small[OFF_NCNT + dst[i]], 1.0f);
        atomicAdd(&binsE[batch[src[i]]], 1.0f);
    } else if (i < NE + NN) {
        atomicAdd(&binsN[batch[i - NE]], 1.0f);
    }
    __syncthreads();
    if (t < 128) {
        if (binsE[t] != 0.0f) atomicAdd(&g_small[OFF_GCE + t], binsE[t]);
        if (binsN[t] != 0.0f) atomicAdd(&g_small[OFF_GCN + t], binsN[t]);
    }
}

// ---------------- fp32 -> bf16 conversion (8 floats / thread) -------------------
__global__ __launch_bounds__(256) void convert_f2b(
    const float* __restrict__ src, __nv_bfloat16* __restrict__ dst, int n8)
{
    int i = blockIdx.x * 256 + threadIdx.x;
    if (i >= n8) return;
    float4 a = ((const float4*)src)[i * 2];
    float4 b = ((const float4*)src)[i * 2 + 1];
    uint4 o;
    o.x = pack2(a.x, a.y);
    o.y = pack2(a.z, a.w);
    o.z = pack2(b.x, b.y);
    o.w = pack2(b.z, b.w);
    ((uint4*)dst)[i] = o;
}

// ---------------- e2n mean -> bf16 ------------------------------------------------
__global__ __launch_bounds__(256) void conv_e2n()
{
    int i = blockIdx.x * 256 + threadIdx.x;
    if (i >= NN * 64) return;
    int v = i >> 6;
    float inv = 1.0f / fmaxf(g_small[OFF_NCNT + v], 1.0f);
    float4 sv = ((const float4*)g_e2n)[i];
    uint2 o;
    o.x = pack2(sv.x * inv, sv.y * inv);
    o.y = pack2(sv.z * inv, sv.w * inv);
    ((uint2*)g_bq2)[i] = o;
}

// ---------------- convert all weights to bf16 ------------------------------------
struct WSrc { const float* p[9]; };
#define WO0 0
#define WO1 65536
#define WO2 131072
#define WO3 196608
#define WO4 458752
#define WO5 655360
#define WO6 851968
#define WO7 917504
#define WO8 983040
__global__ __launch_bounds__(256) void round_weights(WSrc ws) {
    int f = (blockIdx.x * 256 + threadIdx.x) * 4;
    if (f >= 1048576) return;
    const float* sp; int base;
    if      (f < WO1) { sp = ws.p[0]; base = WO0; }
    else if (f < WO2) { sp = ws.p[1]; base = WO1; }
    else if (f < WO3) { sp = ws.p[2]; base = WO2; }
    else if (f < WO4) { sp = ws.p[3]; base = WO3; }
    else if (f < WO5) { sp = ws.p[4]; base = WO4; }
    else if (f < WO6) { sp = ws.p[5]; base = WO5; }
    else if (f < WO7) { sp = ws.p[6]; base = WO6; }
    else if (f < WO8) { sp = ws.p[7]; base = WO7; }
    else              { sp = ws.p[8]; base = WO8; }
    float4 v = *(const float4*)(sp + (f - base));
    uint2 o;
    o.x = pack2(v.x, v.y);
    o.y = pack2(v.z, v.w);
    *(uint2*)(g_wb + f) = o;
}

// ---------------- TMA-fed bf16 GEMM ----------------------------------------------
// C[M,256] = [ssp](A[M,K] @ W^T) [+R]. Block 128x128, 8 warps, warp tile 32x64,
// TBK=64 bf16 (128B rows, SW128), 3-stage TMA pipe.
// DUAL: grid.x=4 selects (tmW,Cout)/(tmW2,Cout2).
// SC=3: fused edge combine (counts precomputed elsewhere).
// SC=4: fused node combine: o=ssp(acc + R[row] + Q3[batch[row]]), n2g scatter.
#define STG_BYTES 32768u
#define SMEMSZ (3 * 32768 + 1024)

template <int ACT, int ADD, int OUTBF, int SC, int DUAL>
__global__ __launch_bounds__(256, 2) void gemm_b(
    const __grid_constant__ CUtensorMap tmA,
    const __grid_constant__ CUtensorMap tmW,
    const __grid_constant__ CUtensorMap tmW2,
    const float* __restrict__ R, void* __restrict__ Cout, void* __restrict__ Cout2,
    int M, int K,
    const int* __restrict__ src, const int* __restrict__ dst,
    const int* __restrict__ batch)
{
    extern __shared__ float dsm[];
    __shared__ __align__(8) uint64_t mbar_s[3];
    uint32_t smb = (uint32_t)__cvta_generic_to_shared(dsm);
    smb = (smb + 1023u) & ~1023u;
    const uint32_t mb = (uint32_t)__cvta_generic_to_shared(mbar_s);

    const int tid = threadIdx.x;
    const int m0 = blockIdx.y * 128;
    const int halfW = DUAL ? (int)(blockIdx.x >> 1) : 0;
    const int n0 = DUAL ? (int)(blockIdx.x & 1) * 128 : (int)blockIdx.x * 128;
    void* Co = (DUAL && halfW) ? Cout2 : Cout;
    const CUtensorMap* wmap = (DUAL && halfW) ? &tmW2 : &tmW;

    if (tid == 0) {
        mbar_init(mb, 1); mbar_init(mb + 8, 1); mbar_init(mb + 16, 1);
    }
    __syncthreads();

    const int KT = K / 64;
    auto issue = [&](int kt, int s) {
        uint32_t base = smb + (uint32_t)s * STG_BYTES;
        mbar_expect(mb + s * 8, STG_BYTES);
        tma2d(base, &tmA, kt * 64, m0, mb + s * 8);
        tma2d(base + 16384u, wmap, kt * 64, n0, mb + s * 8);
    };
    if (tid == 0) {
        int pre = KT < 3 ? KT : 3;
        for (int i = 0; i < pre; i++) issue(i, i);
    }

    const int lane = tid & 31, warp = tid >> 5;
    const int wm = (warp & 3) * 32;
    const int wn = (warp >> 2) * 64;
    const int gid = lane >> 2, tig = lane & 3;
    const int hA = (lane >> 4) & 1;
    const int hB = (lane >> 3) & 1;
    const int arow = wm + (lane & 15);
    const int brow = wn + ((lane >> 4) & 1) * 8 + (lane & 7);
    const uint32_t aAddr = smb + (uint32_t)(arow * 128);
    const uint32_t bAddr = smb + 16384u + (uint32_t)(brow * 128);
    uint32_t cA[4], cB[4];
#pragma unroll
    for (int ks = 0; ks < 4; ks++) {
        cA[ks] = (uint32_t)(((ks * 2 + hA) ^ (arow & 7)) << 4);
        cB[ks] = (uint32_t)(((ks * 2 + hB) ^ (brow & 7)) << 4);
    }

    float acc[2][8][4];
#pragma unroll
    for (int mt = 0; mt < 2; mt++)
#pragma unroll
        for (int nt = 0; nt < 8; nt++)
#pragma unroll
            for (int i = 0; i < 4; i++) acc[mt][nt][i] = 0.0f;

    for (int kt = 0; kt < KT; kt++) {
        const int s = kt % 3;
        mbar_wait(mb + s * 8, (uint32_t)((kt / 3) & 1));
        const uint32_t so = (uint32_t)s * STG_BYTES;

#pragma unroll
        for (int ks = 0; ks < 4; ks++) {
            uint32_t a[2][4];
#pragma unroll
            for (int mt = 0; mt < 2; mt++)
                ldsm4(a[mt][0], a[mt][1], a[mt][2], a[mt][3],
                      aAddr + so + (uint32_t)(mt * 2048) + cA[ks]);
            uint32_t b0[8], b1[8];
#pragma unroll
            for (int g = 0; g < 4; g++)
                ldsm4(b0[2 * g], b1[2 * g], b0[2 * g + 1], b1[2 * g + 1],
                      bAddr + so + (uint32_t)(g * 2048) + cB[ks]);
#pragma unroll
            for (int mt = 0; mt < 2; mt++)
#pragma unroll
                for (int nt = 0; nt < 8; nt++)
                    mma_bf16(acc[mt][nt], a[mt][0], a[mt][1], a[mt][2],
                             a[mt][3], b0[nt], b1[nt]);
        }
        __syncthreads();
        if (tid == 0 && kt + 3 < KT) issue(kt + 3, s);
    }

    // ================= SC=3: fused edge combine (warp-per-edge) =================
    if (SC == 3) {
        float* sacc = dsm + ((smb - (uint32_t)__cvta_generic_to_shared(dsm)) >> 2);
#pragma unroll
        for (int mt = 0; mt < 2; mt++)
#pragma unroll
            for (int half = 0; half < 2; half++) {
                int r = wm + mt * 16 + half * 8 + gid;
#pragma unroll
                for (int nt = 0; nt < 8; nt++) {
                    int c = wn + nt * 8 + tig * 2;
                    *(float2*)&sacc[r * 132 + c] =
                        make_float2(acc[mt][nt][half * 2 + 0],
                                    acc[mt][nt][half * 2 + 1]);
                }
            }
        __syncthreads();

        const int cl = lane * 4;
#pragma unroll 2
        for (int it = 0; it < 16; it++) {
            int el = it * 8 + warp;
            int er = m0 + el;
            if (er >= M) continue;
            int s_ = src[er], d_ = dst[er], b_ = batch[s_];
            float4 a = *(const float4*)&sacc[el * 132 + cl];
            float4 p1 = __ldg((const float4*)(g_p1 + (size_t)s_ * 256 + n0 + cl));
            float4 p2 = __ldg((const float4*)(g_p2 + (size_t)d_ * 256 + n0 + cl));
            float4 p4 = __ldg((const float4*)(g_p4 + (size_t)b_ * 256 + n0 + cl));
            float o0 = ssp(a.x + p1.x + p2.x + p4.x);
            float o1 = ssp(a.y + p1.y + p2.y + p4.y);
            float o2 = ssp(a.z + p1.z + p2.z + p4.z);
            float o3 = ssp(a.w + p1.w + p2.w + p4.w);
            red4(g_e2n + (size_t)d_ * 256 + n0 + cl, o0, o1, o2, o3);
            red4(g_small + OFF_E2G + b_ * 256 + n0 + cl, o0, o1, o2, o3);
            uint2 ov; ov.x = pack2(o0, o1); ov.y = pack2(o2, o3);
            *(uint2*)(g_bemid + (size_t)er * 256 + n0 + cl) = ov;
        }
        return;
    }

    // ================= normal epilogue =================
    int* sbt = (int*)dsm;
    if (SC == 4) {
        if (tid < 128) sbt[tid] = batch[min(m0 + tid, M - 1)];
        __syncthreads();
    }

#pragma unroll
    for (int mt = 0; mt < 2; mt++) {
#pragma unroll
        for (int half = 0; half < 2; half++) {
            int r = wm + mt * 16 + half * 8 + gid;
            int gr = m0 + r;
            if (gr >= M) continue;
#pragma unroll
            for (int nt = 0; nt < 8; nt++) {
                int col = n0 + wn + nt * 8 + tig * 2;
                float o0 = acc[mt][nt][half * 2 + 0];
                float o1 = acc[mt][nt][half * 2 + 1];
                if (SC == 4) {
                    float2 q1v = *(const float2*)&R[(size_t)gr * 256 + col];
                    const float* q3f = (const float*)dst;
                    float2 q3v = *(const float2*)&q3f[(size_t)sbt[r] * 256 + col];
                    o0 = ssp(o0 + q1v.x + q3v.x);
                    o1 = ssp(o1 + q1v.y + q3v.y);
                    atomicAdd(&g_small[OFF_N2G + sbt[r] * 256 + col], o0);
                    atomicAdd(&g_small[OFF_N2G + sbt[r] * 256 + col + 1], o1);
                } else {
                    if (ACT) { o0 = ssp(o0); o1 = ssp(o1); }
                    if (ADD) {
                        float2 rv = *(const float2*)&R[(size_t)gr * 256 + col];
                        o0 += rv.x; o1 += rv.y;
                    }
                }
                if (OUTBF) {
                    ((uint32_t*)Co)[((size_t)gr * 256 + col) >> 1] = pack2(o0, o1);
                } else {
                    *(float2*)&((float*)Co)[(size_t)gr * 256 + col] =
                        make_float2(o0, o1);
                }
            }
        }
    }
}

// ---------------- glob_in = [n2g_mean, e2g_mean, g1] (bf16) ---------------------
__global__ __launch_bounds__(192) void build_glob_in()
{
    int gi = blockIdx.x;
    int t = threadIdx.x;
    int seg = t / 64, w = t % 64;
    uint2 val;
    if (seg == 0) {
        float inv = 1.0f / fmaxf(g_small[OFF_GCN + gi], 1.0f);
        float4 sv = *(const float4*)&g_small[OFF_N2G + gi * 256 + w * 4];
        val.x = pack2(sv.x * inv, sv.y * inv);
        val.y = pack2(sv.z * inv, sv.w * inv);
    } else if (seg == 1) {
        float inv = 1.0f / fmaxf(g_small[OFF_GCE + gi], 1.0f);
        float4 sv = *(const float4*)&g_small[OFF_E2G + gi * 256 + w * 4];
        val.x = pack2(sv.x * inv, sv.y * inv);
        val.y = pack2(sv.z * inv, sv.w * inv);
    } else {
        val = ((const uint2*)g_bg1)[(size_t)gi * 64 + w];
    }
    ((uint2*)g_bgin)[(size_t)gi * 192 + t] = val;
}

// ---------------- host side -------------------------------------------------------
template <typename T>
static T* sym(const void* symbol) {
    void* p = nullptr;
    cudaGetSymbolAddress(&p, symbol);
    return (T*)p;
}

typedef CUresult (*PFN_encode)(
    CUtensorMap*, CUtensorMapDataType, cuuint32_t, void*,
    const cuuint64_t*, const cuuint64_t*, const cuuint32_t*, const cuuint32_t*,
    CUtensorMapInterleave, CUtensorMapSwizzle, CUtensorMapL2promotion,
    CUtensorMapFloatOOBfill);

static void encB(PFN_encode fn, CUtensorMap* m, const void* base,
                 unsigned long long kElems, unsigned long long rows,
                 unsigned long long rowStrideBytes) {
    cuuint64_t dims[2] = {kElems, rows};
    cuuint64_t st[1] = {rowStrideBytes};
    cuuint32_t box[2] = {64u, 128u};
    cuuint32_t es[2] = {1u, 1u};
    fn(m, CU_TENSOR_MAP_DATA_TYPE_BFLOAT16, 2, (void*)base, dims, st, box, es,
       CU_TENSOR_MAP_INTERLEAVE_NONE, CU_TENSOR_MAP_SWIZZLE_128B,
       CU_TENSOR_MAP_L2_PROMOTION_L2_128B, CU_TENSOR_MAP_FLOAT_OOB_FILL_NONE);
}

extern "C" void kernel_launch(void* const* d_in, const int* in_sizes, int n_in,
                              void* d_out, int out_size) {
    const float* node_feats = (const float*)d_in[0];
    const float* edge_feats = (const float*)d_in[1];
    const float* glob_feats = (const float*)d_in[2];
    const int*   edge_index = (const int*)d_in[3];
    const int*   batch      = (const int*)d_in[4];

    const int* src = edge_index;
    const int* dst = edge_index + NE;

    float* out = (float*)d_out;
    float* out_n = out;
    float* out_e = out + (size_t)NN * 256;
    float* out_g = out + (size_t)(NN + NE) * 256;

    __nv_bfloat16* p_bnode = sym<__nv_bfloat16>(g_bnode);
    __nv_bfloat16* p_bedge = sym<__nv_bfloat16>(g_bedge);
    __nv_bfloat16* p_bglob = sym<__nv_bfloat16>(g_bglob);
    __nv_bfloat16* p_bn1   = sym<__nv_bfloat16>(g_bn1);
    __nv_bfloat16* p_be1   = sym<__nv_bfloat16>(g_be1);
    __nv_bfloat16* p_bg1   = sym<__nv_bfloat16>(g_bg1);
    __nv_bfloat16* p_bq2   = sym<__nv_bfloat16>(g_bq2);
    __nv_bfloat16* p_bgin  = sym<__nv_bfloat16>(g_bgin);
    __nv_bfloat16* p_bnmid = sym<__nv_bfloat16>(g_bnmid);
    __nv_bfloat16* p_bemid = sym<__nv_bfloat16>(g_bemid);
    __nv_bfloat16* p_bgmid = sym<__nv_bfloat16>(g_bgmid);
    __nv_bfloat16* p_wb    = sym<__nv_bfloat16>(g_wb);
    float* p_p1 = sym<float>(g_p1);
    float* p_p2 = sym<float>(g_p2);
    float* p_p4 = sym<float>(g_p4);
    float* p_q1 = sym<float>(g_q1);
    float* p_q3 = sym<float>(g_q3);
    float* p_e2n = sym<float>(g_e2n);
    float* p_small = sym<float>(g_small);

    PFN_encode encfn = nullptr;
    {
        void* fp = nullptr;
        cudaDriverEntryPointQueryResult qr;
        cudaGetDriverEntryPoint("cuTensorMapEncodeTiled", &fp,
                                cudaEnableDefault, &qr);
        encfn = (PFN_encode)fp;
    }

    static cudaStream_t sA = nullptr, sB = nullptr, sC = nullptr;
    static cudaEvent_t evStart, evRoot, evZ, evCnt, evA, evQ1, evB, evQ3, evP3, evC, evN, evA2;
    if (!sA) {
        cudaStreamCreateWithFlags(&sA, cudaStreamNonBlocking);
        cudaStreamCreateWithFlags(&sB, cudaStreamNonBlocking);
        cudaStreamCreateWithFlags(&sC, cudaStreamNonBlocking);
        cudaEventCreateWithFlags(&evStart, cudaEventDisableTiming);
        cudaEventCreateWithFlags(&evRoot, cudaEventDisableTiming);
        cudaEventCreateWithFlags(&evZ, cudaEventDisableTiming);
        cudaEventCreateWithFlags(&evCnt, cudaEventDisableTiming);
        cudaEventCreateWithFlags(&evA, cudaEventDisableTiming);
        cudaEventCreateWithFlags(&evQ1, cudaEventDisableTiming);
        cudaEventCreateWithFlags(&evB, cudaEventDisableTiming);
        cudaEventCreateWithFlags(&evQ3, cudaEventDisableTiming);
        cudaEventCreateWithFlags(&evP3, cudaEventDisableTiming);
        cudaEventCreateWithFlags(&evC, cudaEventDisableTiming);
        cudaEventCreateWithFlags(&evN, cudaEventDisableTiming);
        cudaEventCreateWithFlags(&evA2, cudaEventDisableTiming);
    }

    // ---- tensormaps
    CUtensorMap mA_node, mA_edge, mA_glob, mA_n1, mA_e1, mA_g1;
    CUtensorMap mA_q2, mA_gin, mA_nmid, mA_emid, mA_gmid;
    encB(encfn, &mA_node, p_bnode, 256, NN, 512);
    encB(encfn, &mA_edge, p_bedge, 256, NE, 512);
    encB(encfn, &mA_glob, p_bglob, 256, NG, 512);
    encB(encfn, &mA_n1, p_bn1, 256, NN, 512);
    encB(encfn, &mA_e1, p_be1, 256, NE, 512);
    encB(encfn, &mA_g1, p_bg1, 256, NG, 512);
    encB(encfn, &mA_q2, p_bq2, 256, NN, 512);
    encB(encfn, &mA_gin, p_bgin, 768, NG, 1536);
    encB(encfn, &mA_nmid, p_bnmid, 256, NN, 512);
    encB(encfn, &mA_emid, p_bemid, 256, NE, 512);
    encB(encfn, &mA_gmid, p_bgmid, 256, NG, 512);

    CUtensorMap mW_n1, mW_e1, mW_g1, mW_p1, mW_p2, mW_p3, mW_p4;
    CUtensorMap mW_nma, mW_nmb, mW_nmc, mW_gmlp, mW_n2, mW_e2, mW_g2;
    encB(encfn, &mW_n1, p_wb + WO0, 256, 256, 512);
    encB(encfn, &mW_e1, p_wb + WO1, 256, 256, 512);
    encB(encfn, &mW_g1, p_wb + WO2, 256, 256, 512);
    encB(encfn, &mW_p1, p_wb + WO3 + 0,   256, 256, 2048);
    encB(encfn, &mW_p2, p_wb + WO3 + 256, 256, 256, 2048);
    encB(encfn, &mW_p3, p_wb + WO3 + 512, 256, 256, 2048);
    encB(encfn, &mW_p4, p_wb + WO3 + 768, 256, 256, 2048);
    encB(encfn, &mW_nma, p_wb + WO4 + 0,   256, 256, 1536);
    encB(encfn, &mW_nmb, p_wb + WO4 + 256, 256, 256, 1536);
    encB(encfn, &mW_nmc, p_wb + WO4 + 512, 256, 256, 1536);
    encB(encfn, &mW_gmlp, p_wb + WO5, 768, 256, 1536);
    encB(encfn, &mW_n2, p_wb + WO6, 256, 256, 512);
    encB(encfn, &mW_e2, p_wb + WO7, 256, 256, 512);
    encB(encfn, &mW_g2, p_wb + WO8, 256, 256, 512);

    cudaFuncSetAttribute(gemm_b<1,0,1,0,0>, cudaFuncAttributeMaxDynamicSharedMemorySize, SMEMSZ);
    cudaFuncSetAttribute(gemm_b<0,0,0,0,0>, cudaFuncAttributeMaxDynamicSharedMemorySize, SMEMSZ);
    cudaFuncSetAttribute(gemm_b<0,0,0,0,1>, cudaFuncAttributeMaxDynamicSharedMemorySize, SMEMSZ);
    cudaFuncSetAttribute(gemm_b<0,0,0,3,0>, cudaFuncAttributeMaxDynamicSharedMemorySize, SMEMSZ);
    cudaFuncSetAttribute(gemm_b<1,0,1,4,0>, cudaFuncAttributeMaxDynamicSharedMemorySize, SMEMSZ);
    cudaFuncSetAttribute(gemm_b<1,1,0,0,0>, cudaFuncAttributeMaxDynamicSharedMemorySize, SMEMSZ);

    const int BN_N = (NN + 127) / 128;
    const int BN_E = (NE + 127) / 128;
    WSrc ws;
    for (int i = 0; i < 9; i++) ws.p[i] = (const float*)d_in[5 + i];

    cudaEventRecord(evStart, 0);

    // ---- stream B: weight rounding FIRST, then zeros, then glob chain
    cudaStreamWaitEvent(sB, evStart, 0);
    round_weights<<<1024, 256, 0, sB>>>(ws);
    cudaEventRecord(evRoot, sB);
    zero_kernel<<<(NN * 256 + 255) / 256, 256, 0, sB>>>(p_e2n, NN * 256);
    zero_kernel<<<(SMALL_N + 255) / 256, 256, 0, sB>>>(p_small, SMALL_N);
    cudaEventRecord(evZ, sB);
    convert_f2b<<<(NG * 32 + 255) / 256, 256, 0, sB>>>(glob_feats, p_bglob, NG * 32);
    gemm_b<1,0,1,0,0><<<dim3(2, 1), 256, SMEMSZ, sB>>>(mA_glob, mW_g1, mW_g1, nullptr, p_bg1, nullptr, NG, 256, nullptr, nullptr, nullptr);
    gemm_b<0,0,0,0,1><<<dim3(4, 1), 256, SMEMSZ, sB>>>(mA_g1, mW_p4, mW_nmc, nullptr, p_p4, p_q3, NG, 256, nullptr, nullptr, nullptr);
    cudaEventRecord(evB, sB);
    cudaEventRecord(evQ3, sB);

    // ---- stream C: degree counts (smem-aggregated), off critical path
    cudaStreamWaitEvent(sC, evZ, 0);
    count_kernel<<<(NE + NN + 255) / 256, 256, 0, sC>>>(src, dst, batch);
    cudaEventRecord(evCnt, sC);

    // ---- stream A: node chain (conv -> n1 -> P1P2(dual) -> Q1)
    cudaStreamWaitEvent(sA, evStart, 0);
    convert_f2b<<<(NN * 32 + 255) / 256, 256, 0, sA>>>(node_feats, p_bnode, NN * 32);
    cudaStreamWaitEvent(sA, evRoot, 0);
    gemm_b<1,0,1,0,0><<<dim3(2, BN_N), 256, SMEMSZ, sA>>>(mA_node, mW_n1, mW_n1, nullptr, p_bn1, nullptr, NN, 256, nullptr, nullptr, nullptr);
    gemm_b<0,0,0,0,1><<<dim3(4, BN_N), 256, SMEMSZ, sA>>>(mA_n1, mW_p1, mW_p2, nullptr, p_p1, p_p2, NN, 256, nullptr, nullptr, nullptr);
    cudaEventRecord(evA, sA);
    gemm_b<0,0,0,0,0><<<dim3(2, BN_N), 256, SMEMSZ, sA>>>(mA_n1, mW_nma, mW_nma, nullptr, p_q1, nullptr, NN, 256, nullptr, nullptr, nullptr);
    cudaEventRecord(evQ1, sA);

    // ---- default stream: edge chain (conv -> e1 -> P3+combine)
    convert_f2b<<<(NE * 32 + 255) / 256, 256>>>(edge_feats, p_bedge, NE * 32);
    cudaStreamWaitEvent(0, evRoot, 0);
    gemm_b<1,0,1,0,0><<<dim3(2, BN_E), 256, SMEMSZ>>>(mA_edge, mW_e1, mW_e1, nullptr, p_be1, nullptr, NE, 256, nullptr, nullptr, nullptr);
    cudaStreamWaitEvent(0, evA, 0);
    cudaStreamWaitEvent(0, evB, 0);
    gemm_b<0,0,0,3,0><<<dim3(2, BN_E), 256, SMEMSZ>>>(mA_e1, mW_p3, mW_p3, nullptr, p_bemid, nullptr, NE, 256, src, dst, batch);
    cudaEventRecord(evP3, 0);

    // ---- stream C: out_e (needs only emid)
    cudaStreamWaitEvent(sC, evP3, 0);
    gemm_b<1,1,0,0,0><<<dim3(2, BN_E), 256, SMEMSZ, sC>>>(mA_emid, mW_e2, mW_e2, edge_feats, out_e, nullptr, NE, 256, nullptr, nullptr, nullptr);
    cudaEventRecord(evC, sC);

    // ---- default: node combine (conv e2n mean -> Q2 with fused combine)
    cudaStreamWaitEvent(0, evCnt, 0);
    conv_e2n<<<(NN * 64 + 255) / 256, 256>>>();
    cudaStreamWaitEvent(0, evQ1, 0);
    cudaStreamWaitEvent(0, evQ3, 0);
    gemm_b<1,0,1,4,0><<<dim3(2, BN_N), 256, SMEMSZ>>>(mA_q2, mW_nmb, mW_nmb, p_q1, p_bnmid, nullptr, NN, 256, nullptr, (const int*)p_q3, batch);
    cudaEventRecord(evN, 0);

    // ---- stream A: out_n overlaps global model
    cudaStreamWaitEvent(sA, evN, 0);
    gemm_b<1,1,0,0,0><<<dim3(2, BN_N), 256, SMEMSZ, sA>>>(mA_nmid, mW_n2, mW_n2, node_feats, out_n, nullptr, NN, 256, nullptr, nullptr, nullptr);
    cudaEventRecord(evA2, sA);

    // ---- default: global model + out_g
    build_glob_in<<<NG, 192>>>();
    gemm_b<1,0,1,0,0><<<dim3(2, 1), 256, SMEMSZ>>>(mA_gin, mW_gmlp, mW_gmlp, nullptr, p_bgmid, nullptr, NG, 768, nullptr, nullptr, nullptr);
    gemm_b<1,1,0,0,0><<<dim3(2, 1), 256, SMEMSZ>>>(mA_gmid, mW_g2, mW_g2, glob_feats, out_g, nullptr, NG, 256, nullptr, nullptr, nullptr);

    // ---- rejoin side streams
    cudaStreamWaitEvent(0, evC, 0);
    cudaStreamWaitEvent(0, evA2, 0);
}